// round 2
// baseline (speedup 1.0000x reference)
#include <cuda_runtime.h>

// GraphSAGE 2-layer: N=100000 nodes, E=1600000 edges, dims 32 -> 64 -> 32.
// Pipeline:
//   K0: zero g_agg
//   K1: scatter  g_agg[dst] += x[src]                (32 floats/edge, warp-per-edge)
//   K2: fused per-node MLP:
//         h = relu(Wl_in @ agg + b_in + Wr_in @ x)   (64)
//         g = Wl_out @ h                             (32)  -> g_g
//         out = Wr_out @ h + b_out                   (32)  -> d_out (init)
//   K3: scatter  out[dst] += g_g[src]                (32 floats/edge)
// Layer-2 projection applied BEFORE the scatter (linear commutes with sum),
// halving layer-2 atomic traffic (32 dims instead of 64).
//
// NOTE: edge_index is int32 on device (JAX x64 disabled downcasts int64->int32).

#define MAX_NODES 100000
#define D 32

__device__ float g_agg[MAX_NODES * D];   // segment-sum of x
__device__ float g_g[MAX_NODES * D];     // h @ Wl_out^T  (scatter payload for layer 2)

// ---------------------------------------------------------------------------
__global__ void zero_agg_kernel(int n) {
    int i = blockIdx.x * blockDim.x + threadIdx.x;
    if (i < n) g_agg[i] = 0.0f;
}

// ---------------------------------------------------------------------------
// Warp per edge; lane = feature. Coalesced gather + coalesced 128B atomic burst.
__global__ void scatter_x_kernel(const float* __restrict__ x,
                                 const int* __restrict__ src,
                                 const int* __restrict__ dst,
                                 int E) {
    int lane = threadIdx.x & 31;
    int e = (blockIdx.x * blockDim.x + threadIdx.x) >> 5;
    if (e >= E) return;
    int s = src[e];
    int d = dst[e];
    float v = __ldg(&x[s * D + lane]);
    atomicAdd(&g_agg[d * D + lane], v);
}

__global__ void scatter_g_kernel(float* __restrict__ out,
                                 const int* __restrict__ src,
                                 const int* __restrict__ dst,
                                 int E) {
    int lane = threadIdx.x & 31;
    int e = (blockIdx.x * blockDim.x + threadIdx.x) >> 5;
    if (e >= E) return;
    int s = src[e];
    int d = dst[e];
    float v = g_g[s * D + lane];
    atomicAdd(&out[d * D + lane], v);
}

// ---------------------------------------------------------------------------
// Fused MLP: warp per node. Lane L holds h[2L], h[2L+1] (64 hidden dims).
// Inputs broadcast across the warp via shuffles; weights staged in shared
// memory in transposed float2 layout so every LDS.64 is conflict-free.
__global__ void fused_mlp_kernel(const float* __restrict__ x,
                                 const float* __restrict__ Wli,  // [64,32]
                                 const float* __restrict__ bli,  // [64]
                                 const float* __restrict__ Wri,  // [64,32]
                                 const float* __restrict__ Wlo,  // [32,64]
                                 const float* __restrict__ blo,  // [32]
                                 const float* __restrict__ Wro,  // [32,64]
                                 float* __restrict__ out,
                                 int N) {
    // w1l[k][m] = {Wli[2m][k], Wli[2m+1][k]}   (stage-1, indexed by input dim k)
    // w2l[m][o] = {Wlo[o][2m], Wlo[o][2m+1]}   (stage-2, indexed by hidden pair m)
    __shared__ float2 w1l[32][32];
    __shared__ float2 w1r[32][32];
    __shared__ float2 w2l[32][32];
    __shared__ float2 w2r[32][32];
    __shared__ float bsh[64];
    __shared__ float bosh[32];

    int tid = threadIdx.x;
    for (int idx = tid; idx < 1024; idx += blockDim.x) {
        int k = idx >> 5, m = idx & 31;           // stage-1 layout
        w1l[k][m] = make_float2(Wli[(2 * m) * 32 + k], Wli[(2 * m + 1) * 32 + k]);
        w1r[k][m] = make_float2(Wri[(2 * m) * 32 + k], Wri[(2 * m + 1) * 32 + k]);
        int mm = idx >> 5, o = idx & 31;          // stage-2 layout
        w2l[mm][o] = make_float2(Wlo[o * 64 + 2 * mm], Wlo[o * 64 + 2 * mm + 1]);
        w2r[mm][o] = make_float2(Wro[o * 64 + 2 * mm], Wro[o * 64 + 2 * mm + 1]);
    }
    if (tid < 64) bsh[tid] = bli[tid];
    if (tid < 32) bosh[tid] = blo[tid];
    __syncthreads();

    int lane = tid & 31;
    int warp = (blockIdx.x * blockDim.x + tid) >> 5;
    int nwarps = (gridDim.x * blockDim.x) >> 5;

    for (int node = warp; node < N; node += nwarps) {
        float a  = g_agg[node * D + lane];
        float xv = x[node * D + lane];

        float h0 = bsh[2 * lane];
        float h1 = bsh[2 * lane + 1];
        #pragma unroll
        for (int k = 0; k < 32; k++) {
            float av = __shfl_sync(0xffffffffu, a, k);
            float xx = __shfl_sync(0xffffffffu, xv, k);
            float2 wl = w1l[k][lane];
            float2 wr = w1r[k][lane];
            h0 += wl.x * av + wr.x * xx;
            h1 += wl.y * av + wr.y * xx;
        }
        h0 = fmaxf(h0, 0.0f);
        h1 = fmaxf(h1, 0.0f);

        float g = 0.0f;
        float r = bosh[lane];
        #pragma unroll
        for (int m = 0; m < 32; m++) {
            float hv0 = __shfl_sync(0xffffffffu, h0, m);  // h[2m]
            float hv1 = __shfl_sync(0xffffffffu, h1, m);  // h[2m+1]
            float2 wl = w2l[m][lane];
            float2 wr = w2r[m][lane];
            g += wl.x * hv0 + wl.y * hv1;
            r += wr.x * hv0 + wr.y * hv1;
        }

        g_g[node * D + lane] = g;
        out[node * D + lane] = r;   // init out with lin_r part; K3 adds scatter
    }
}

// ---------------------------------------------------------------------------
extern "C" void kernel_launch(void* const* d_in, const int* in_sizes, int n_in,
                              void* d_out, int out_size) {
    const float* x   = (const float*)d_in[0];
    const int*   ei  = (const int*)d_in[1];
    const float* Wli = (const float*)d_in[2];
    const float* bli = (const float*)d_in[3];
    const float* Wri = (const float*)d_in[4];
    const float* Wlo = (const float*)d_in[5];
    const float* blo = (const float*)d_in[6];
    const float* Wro = (const float*)d_in[7];
    float* out = (float*)d_out;

    int N = in_sizes[0] / D;      // 100000
    int E = in_sizes[1] / 2;      // 1600000
    const int* src = ei;
    const int* dst = ei + E;

    // K0: zero aggregation buffer
    {
        int n = N * D;
        zero_agg_kernel<<<(n + 255) / 256, 256>>>(n);
    }
    // K1: scatter x into g_agg (warp per edge)
    {
        int blocks = (E + 7) / 8;          // 8 warps (edges) per 256-thread block
        scatter_x_kernel<<<blocks, 256>>>(x, src, dst, E);
    }
    // K2: fused node-wise MLP (grid-stride, warp per node)
    {
        fused_mlp_kernel<<<592, 256>>>(x, Wli, bli, Wri, Wlo, blo, Wro, out, N);
    }
    // K3: scatter g into out
    {
        int blocks = (E + 7) / 8;
        scatter_g_kernel<<<blocks, 256>>>(out, src, dst, E);
    }
}

// round 3
// speedup vs baseline: 1.6571x; 1.6571x over previous
#include <cuda_runtime.h>

// GraphSAGE 2-layer: N=100000 nodes, E=1600000 edges, dims 32 -> 64 -> 32.
//   K0: zero g_agg
//   K1: scatter  g_agg[dst] += x[src]     (8 threads/edge, v4 RED atomics)
//   K2: fused per-node MLP (warp per node)
//   K3: scatter  out[dst] += g_g[src]     (8 threads/edge, v4 RED atomics)
// Layer-2 projection applied BEFORE the scatter (linear commutes with sum).
// edge_index is int32 on device.

#define MAX_NODES 100000
#define D 32

__device__ float g_agg[MAX_NODES * D];
__device__ float g_g[MAX_NODES * D];

__device__ __forceinline__ void red_add_v4(float* addr, float4 v) {
    asm volatile("red.global.add.v4.f32 [%0], {%1, %2, %3, %4};"
                 :: "l"(addr), "f"(v.x), "f"(v.y), "f"(v.z), "f"(v.w)
                 : "memory");
}

// ---------------------------------------------------------------------------
__global__ void zero_agg_kernel(int n4) {
    int i = blockIdx.x * blockDim.x + threadIdx.x;
    if (i < n4) ((float4*)g_agg)[i] = make_float4(0.f, 0.f, 0.f, 0.f);
}

// ---------------------------------------------------------------------------
// 8 threads per edge; quad q handles floats [4q, 4q+4). One v4 RED per thread.
__global__ void scatter_x_kernel(const float* __restrict__ x,
                                 const int* __restrict__ src,
                                 const int* __restrict__ dst,
                                 int E) {
    int t = blockIdx.x * blockDim.x + threadIdx.x;
    int e = t >> 3;
    int q = (t & 7) << 2;          // float offset within row
    if (e >= E) return;
    int s = __ldg(&src[e]);
    int d = __ldg(&dst[e]);
    float4 v = *(const float4*)&x[s * D + q];
    red_add_v4(&g_agg[d * D + q], v);
}

__global__ void scatter_g_kernel(float* __restrict__ out,
                                 const int* __restrict__ src,
                                 const int* __restrict__ dst,
                                 int E) {
    int t = blockIdx.x * blockDim.x + threadIdx.x;
    int e = t >> 3;
    int q = (t & 7) << 2;
    if (e >= E) return;
    int s = __ldg(&src[e]);
    int d = __ldg(&dst[e]);
    float4 v = *(const float4*)&g_g[s * D + q];
    red_add_v4(&out[d * D + q], v);
}

// ---------------------------------------------------------------------------
// Fused MLP: warp per node. Lane L holds h[2L], h[2L+1] (64 hidden dims).
__global__ void fused_mlp_kernel(const float* __restrict__ x,
                                 const float* __restrict__ Wli,  // [64,32]
                                 const float* __restrict__ bli,  // [64]
                                 const float* __restrict__ Wri,  // [64,32]
                                 const float* __restrict__ Wlo,  // [32,64]
                                 const float* __restrict__ blo,  // [32]
                                 const float* __restrict__ Wro,  // [32,64]
                                 float* __restrict__ out,
                                 int N) {
    __shared__ float2 w1l[32][32];
    __shared__ float2 w1r[32][32];
    __shared__ float2 w2l[32][32];
    __shared__ float2 w2r[32][32];
    __shared__ float bsh[64];
    __shared__ float bosh[32];

    int tid = threadIdx.x;
    for (int idx = tid; idx < 1024; idx += blockDim.x) {
        int k = idx >> 5, m = idx & 31;
        w1l[k][m] = make_float2(Wli[(2 * m) * 32 + k], Wli[(2 * m + 1) * 32 + k]);
        w1r[k][m] = make_float2(Wri[(2 * m) * 32 + k], Wri[(2 * m + 1) * 32 + k]);
        w2l[k][m] = make_float2(Wlo[m * 64 + 2 * k], Wlo[m * 64 + 2 * k + 1]);
        w2r[k][m] = make_float2(Wro[m * 64 + 2 * k], Wro[m * 64 + 2 * k + 1]);
    }
    if (tid < 64) bsh[tid] = bli[tid];
    if (tid < 32) bosh[tid] = blo[tid];
    __syncthreads();

    int lane = tid & 31;
    int warp = (blockIdx.x * blockDim.x + tid) >> 5;
    int nwarps = (gridDim.x * blockDim.x) >> 5;

    for (int node = warp; node < N; node += nwarps) {
        float a  = g_agg[node * D + lane];
        float xv = x[node * D + lane];

        float h0 = bsh[2 * lane];
        float h1 = bsh[2 * lane + 1];
        #pragma unroll
        for (int k = 0; k < 32; k++) {
            float av = __shfl_sync(0xffffffffu, a, k);
            float xx = __shfl_sync(0xffffffffu, xv, k);
            float2 wl = w1l[k][lane];
            float2 wr = w1r[k][lane];
            h0 += wl.x * av + wr.x * xx;
            h1 += wl.y * av + wr.y * xx;
        }
        h0 = fmaxf(h0, 0.0f);
        h1 = fmaxf(h1, 0.0f);

        float g = 0.0f;
        float r = bosh[lane];
        #pragma unroll
        for (int m = 0; m < 32; m++) {
            float hv0 = __shfl_sync(0xffffffffu, h0, m);
            float hv1 = __shfl_sync(0xffffffffu, h1, m);
            float2 wl = w2l[m][lane];
            float2 wr = w2r[m][lane];
            g += wl.x * hv0 + wl.y * hv1;
            r += wr.x * hv0 + wr.y * hv1;
        }

        g_g[node * D + lane] = g;
        out[node * D + lane] = r;
    }
}

// ---------------------------------------------------------------------------
extern "C" void kernel_launch(void* const* d_in, const int* in_sizes, int n_in,
                              void* d_out, int out_size) {
    const float* x   = (const float*)d_in[0];
    const int*   ei  = (const int*)d_in[1];
    const float* Wli = (const float*)d_in[2];
    const float* bli = (const float*)d_in[3];
    const float* Wri = (const float*)d_in[4];
    const float* Wlo = (const float*)d_in[5];
    const float* blo = (const float*)d_in[6];
    const float* Wro = (const float*)d_in[7];
    float* out = (float*)d_out;

    int N = in_sizes[0] / D;      // 100000
    int E = in_sizes[1] / 2;      // 1600000
    const int* src = ei;
    const int* dst = ei + E;

    {   // K0: zero aggregation buffer (float4 stores)
        int n4 = N * D / 4;
        zero_agg_kernel<<<(n4 + 255) / 256, 256>>>(n4);
    }
    {   // K1: scatter x into g_agg — 8 threads/edge, 32 edges per 256-thread block
        int blocks = (E + 31) / 32;
        scatter_x_kernel<<<blocks, 256>>>(x, src, dst, E);
    }
    {   // K2: fused node-wise MLP
        fused_mlp_kernel<<<592, 256>>>(x, Wli, bli, Wri, Wlo, blo, Wro, out, N);
    }
    {   // K3: scatter g into out
        int blocks = (E + 31) / 32;
        scatter_g_kernel<<<blocks, 256>>>(out, src, dst, E);
    }
}

// round 4
// speedup vs baseline: 1.9323x; 1.1661x over previous
#include <cuda_runtime.h>

// GraphSAGE 2-layer: N=100000 nodes, E=1600000 edges, dims 32 -> 64 -> 32.
//   K0: zero g_agg
//   K1: scatter  g_agg[dst] += x[src]     (8 threads/edge, v4 RED atomics)
//   K2: fused per-node MLP (THREAD per node, broadcast weights from smem)
//   K3: scatter  out[dst] += g_g[src]     (8 threads/edge, v4 RED atomics)
// Layer-2 projection applied BEFORE the scatter (linear commutes with sum).
// edge_index is int32 on device.

#define MAX_NODES 100000
#define D 32

__device__ float g_agg[MAX_NODES * D];
__device__ float g_g[MAX_NODES * D];

__device__ __forceinline__ void red_add_v4(float* addr, float4 v) {
    asm volatile("red.global.add.v4.f32 [%0], {%1, %2, %3, %4};"
                 :: "l"(addr), "f"(v.x), "f"(v.y), "f"(v.z), "f"(v.w)
                 : "memory");
}

// ---------------------------------------------------------------------------
__global__ void zero_agg_kernel(int n4) {
    int i = blockIdx.x * blockDim.x + threadIdx.x;
    if (i < n4) ((float4*)g_agg)[i] = make_float4(0.f, 0.f, 0.f, 0.f);
}

// ---------------------------------------------------------------------------
// 8 threads per edge; quad q handles floats [4q, 4q+4). One v4 RED per thread.
__global__ void scatter_x_kernel(const float* __restrict__ x,
                                 const int* __restrict__ src,
                                 const int* __restrict__ dst,
                                 int E) {
    int t = blockIdx.x * blockDim.x + threadIdx.x;
    int e = t >> 3;
    int q = (t & 7) << 2;
    if (e >= E) return;
    int s = __ldg(&src[e]);
    int d = __ldg(&dst[e]);
    float4 v = *(const float4*)&x[s * D + q];
    red_add_v4(&g_agg[d * D + q], v);
}

__global__ void scatter_g_kernel(float* __restrict__ out,
                                 const int* __restrict__ src,
                                 const int* __restrict__ dst,
                                 int E) {
    int t = blockIdx.x * blockDim.x + threadIdx.x;
    int e = t >> 3;
    int q = (t & 7) << 2;
    if (e >= E) return;
    int s = __ldg(&src[e]);
    int d = __ldg(&dst[e]);
    float4 v = *(const float4*)&g_g[s * D + q];
    red_add_v4(&out[d * D + q], v);
}

// ---------------------------------------------------------------------------
// Thread-per-node MLP. All lanes read identical weight addresses (smem
// broadcast, 16B/warp-access) and carry 64 independent accumulators.
//   h = relu(Wli @ agg + b1 + Wri @ x)   (64)
//   g = Wlo @ h            -> g_g        (32)
//   r = Wro @ h + b2       -> out        (32)
// smem weight layouts (transposed for float4-over-output access):
//   w1l[k][m]: Wli[m][k]   (k=0..31 input dim, m=0..63 hidden dim)
//   w2l[m][o]: Wlo[o][m]   (m=0..63 hidden dim, o=0..31 output dim)
__global__ void __launch_bounds__(128)
fused_mlp_kernel(const float* __restrict__ x,
                 const float* __restrict__ Wli,  // [64,32]
                 const float* __restrict__ bli,  // [64]
                 const float* __restrict__ Wri,  // [64,32]
                 const float* __restrict__ Wlo,  // [32,64]
                 const float* __restrict__ blo,  // [32]
                 const float* __restrict__ Wro,  // [32,64]
                 float* __restrict__ out,
                 int N) {
    __shared__ float4 w1l4[32 * 16];   // [k][m4]
    __shared__ float4 w1r4[32 * 16];
    __shared__ float4 w2l4[64 * 8];    // [m][o4]
    __shared__ float4 w2r4[64 * 8];
    __shared__ float4 b1s[16];
    __shared__ float4 b2s[8];

    int tid = threadIdx.x;
    {
        float* w1l = (float*)w1l4;
        float* w1r = (float*)w1r4;
        float* w2l = (float*)w2l4;
        float* w2r = (float*)w2r4;
        for (int idx = tid; idx < 2048; idx += 128) {
            int k = idx >> 6, m = idx & 63;      // stage-1: [k][m]
            w1l[k * 64 + m] = Wli[m * 32 + k];
            w1r[k * 64 + m] = Wri[m * 32 + k];
            int mm = idx >> 5, o = idx & 31;     // stage-2: [m][o]
            w2l[mm * 32 + o] = Wlo[o * 64 + mm];
            w2r[mm * 32 + o] = Wro[o * 64 + mm];
        }
        if (tid < 64) ((float*)b1s)[tid] = bli[tid];
        if (tid < 32) ((float*)b2s)[tid] = blo[tid];
    }
    __syncthreads();

    int node = blockIdx.x * 128 + tid;
    if (node >= N) return;

    // Load this node's agg and x rows into registers.
    float a[32], xv[32];
    {
        const float4* ar = (const float4*)&g_agg[node * D];
        const float4* xr = (const float4*)&x[node * D];
        #pragma unroll
        for (int i = 0; i < 8; i++) {
            float4 t0 = ar[i];
            a[4 * i] = t0.x; a[4 * i + 1] = t0.y; a[4 * i + 2] = t0.z; a[4 * i + 3] = t0.w;
            float4 t1 = xr[i];
            xv[4 * i] = t1.x; xv[4 * i + 1] = t1.y; xv[4 * i + 2] = t1.z; xv[4 * i + 3] = t1.w;
        }
    }

    // Stage 1: h[64] = b1 + Wli@a + Wri@x
    float h[64];
    #pragma unroll
    for (int m4 = 0; m4 < 16; m4++) {
        float4 b = b1s[m4];
        h[4 * m4] = b.x; h[4 * m4 + 1] = b.y; h[4 * m4 + 2] = b.z; h[4 * m4 + 3] = b.w;
    }
    #pragma unroll
    for (int k = 0; k < 32; k++) {
        float av = a[k];
        float xx = xv[k];
        #pragma unroll
        for (int m4 = 0; m4 < 16; m4++) {
            float4 wl = w1l4[k * 16 + m4];
            float4 wr = w1r4[k * 16 + m4];
            h[4 * m4]     = fmaf(wl.x, av, fmaf(wr.x, xx, h[4 * m4]));
            h[4 * m4 + 1] = fmaf(wl.y, av, fmaf(wr.y, xx, h[4 * m4 + 1]));
            h[4 * m4 + 2] = fmaf(wl.z, av, fmaf(wr.z, xx, h[4 * m4 + 2]));
            h[4 * m4 + 3] = fmaf(wl.w, av, fmaf(wr.w, xx, h[4 * m4 + 3]));
        }
    }
    #pragma unroll
    for (int m = 0; m < 64; m++) h[m] = fmaxf(h[m], 0.0f);

    // Stage 2: g = Wlo@h ; r = b2 + Wro@h
    float g[32], r[32];
    #pragma unroll
    for (int o4 = 0; o4 < 8; o4++) {
        float4 b = b2s[o4];
        g[4 * o4] = 0.f; g[4 * o4 + 1] = 0.f; g[4 * o4 + 2] = 0.f; g[4 * o4 + 3] = 0.f;
        r[4 * o4] = b.x; r[4 * o4 + 1] = b.y; r[4 * o4 + 2] = b.z; r[4 * o4 + 3] = b.w;
    }
    #pragma unroll
    for (int m = 0; m < 64; m++) {
        float hv = h[m];
        #pragma unroll
        for (int o4 = 0; o4 < 8; o4++) {
            float4 wl = w2l4[m * 8 + o4];
            float4 wr = w2r4[m * 8 + o4];
            g[4 * o4]     = fmaf(wl.x, hv, g[4 * o4]);
            g[4 * o4 + 1] = fmaf(wl.y, hv, g[4 * o4 + 1]);
            g[4 * o4 + 2] = fmaf(wl.z, hv, g[4 * o4 + 2]);
            g[4 * o4 + 3] = fmaf(wl.w, hv, g[4 * o4 + 3]);
            r[4 * o4]     = fmaf(wr.x, hv, r[4 * o4]);
            r[4 * o4 + 1] = fmaf(wr.y, hv, r[4 * o4 + 1]);
            r[4 * o4 + 2] = fmaf(wr.z, hv, r[4 * o4 + 2]);
            r[4 * o4 + 3] = fmaf(wr.w, hv, r[4 * o4 + 3]);
        }
    }

    float4* gg = (float4*)&g_g[node * D];
    float4* oo = (float4*)&out[node * D];
    #pragma unroll
    for (int o4 = 0; o4 < 8; o4++) {
        gg[o4] = make_float4(g[4 * o4], g[4 * o4 + 1], g[4 * o4 + 2], g[4 * o4 + 3]);
        oo[o4] = make_float4(r[4 * o4], r[4 * o4 + 1], r[4 * o4 + 2], r[4 * o4 + 3]);
    }
}

// ---------------------------------------------------------------------------
extern "C" void kernel_launch(void* const* d_in, const int* in_sizes, int n_in,
                              void* d_out, int out_size) {
    const float* x   = (const float*)d_in[0];
    const int*   ei  = (const int*)d_in[1];
    const float* Wli = (const float*)d_in[2];
    const float* bli = (const float*)d_in[3];
    const float* Wri = (const float*)d_in[4];
    const float* Wlo = (const float*)d_in[5];
    const float* blo = (const float*)d_in[6];
    const float* Wro = (const float*)d_in[7];
    float* out = (float*)d_out;

    int N = in_sizes[0] / D;      // 100000
    int E = in_sizes[1] / 2;      // 1600000
    const int* src = ei;
    const int* dst = ei + E;

    {   // K0: zero aggregation buffer
        int n4 = N * D / 4;
        zero_agg_kernel<<<(n4 + 255) / 256, 256>>>(n4);
    }
    {   // K1: scatter x into g_agg
        int blocks = (E + 31) / 32;
        scatter_x_kernel<<<blocks, 256>>>(x, src, dst, E);
    }
    {   // K2: fused node-wise MLP (thread per node)
        fused_mlp_kernel<<<(N + 127) / 128, 128>>>(x, Wli, bli, Wri, Wlo, blo, Wro, out, N);
    }
    {   // K3: scatter g into out
        int blocks = (E + 31) / 32;
        scatter_g_kernel<<<blocks, 256>>>(out, src, dst, E);
    }
}